// round 12
// baseline (speedup 1.0000x reference)
#include <cuda_runtime.h>
#include <math.h>
#include <stdint.h>

#define BB 64
#define TT 2048
#define DENC 512
#define DRNN 1024
#define DATT 128
#define NFQ 32
#define KW 31
#define PADW 15
#define SMX 16              // blocks per row (128 t's each)

typedef unsigned long long ull;

__device__ float g_pq[BB * DATT];
__device__ float g_part[BB * SMX * DENC];          // unnormalized ctx partials
__device__ __align__(16) float g_dfa[NFQ * DATT];  // densew transposed to [f][a]
__device__ float g_smax[BB * SMX];
__device__ float g_ssum[BB * SMX];

__device__ __forceinline__ float tanh_fast(float x) {
    float y;
    asm("tanh.approx.f32 %0, %1;" : "=f"(y) : "f"(x));
    return y;
}
__device__ __forceinline__ void unpack2(ull v, float& lo, float& hi) {
    asm("mov.b64 {%0, %1}, %2;" : "=f"(lo), "=f"(hi) : "l"(v));
}
__device__ __forceinline__ ull pack2(float lo, float hi) {
    ull r;
    asm("mov.b64 %0, {%1, %2};" : "=l"(r) : "f"(lo), "f"(hi));
    return r;
}
__device__ __forceinline__ ull fma2(ull a, ull b, ull c) {
    ull d;
    asm("fma.rn.f32x2 %0, %1, %2, %3;" : "=l"(d) : "l"(a), "l"(b), "l"(c));
    return d;
}
__device__ __forceinline__ ull add2(ull a, ull b) {
    ull d;
    asm("add.rn.f32x2 %0, %1, %2;" : "=l"(d) : "l"(a), "l"(b));
    return d;
}

// ---------------------------------------------------------------------------
// Kernel A: pq[b,a] = sum_d ahs[b,d] * qw[a,d]   grid (B, 8)
//           blocks with blockIdx.y == 0 also transpose densew -> g_dfa
// ---------------------------------------------------------------------------
__global__ __launch_bounds__(128) void pq_kernel(const float* __restrict__ ahs,
                                                 const float* __restrict__ qw,
                                                 const float* __restrict__ densew) {
    const int b = blockIdx.x;
    const int abase = blockIdx.y * 16;

    // fold prep_dense: first y-slice blocks transpose densew [a][f] -> [f][a]
    if (blockIdx.y == 0) {
        const int i = b * 64 + threadIdx.x % 64;  // 64 elems per block, 64 blocks
        const int base = b * 64;
        if (threadIdx.x < 64) {
            const int idx = base + threadIdx.x;
            const int f = idx >> 7, a = idx & 127;
            g_dfa[idx] = densew[a * NFQ + f];
        }
        (void)i;
    }

    __shared__ __align__(16) float ahs_s[DRNN];
    for (int i = threadIdx.x; i < DRNN / 4; i += 128)
        reinterpret_cast<float4*>(ahs_s)[i] =
            reinterpret_cast<const float4*>(ahs + (size_t)b * DRNN)[i];
    __syncthreads();
    const int w = threadIdx.x >> 5, lane = threadIdx.x & 31;
    #pragma unroll
    for (int aa = 0; aa < 4; aa++) {
        const int a = abase + w * 4 + aa;
        const float4* qr = reinterpret_cast<const float4*>(qw + (size_t)a * DRNN);
        float acc = 0.f;
        #pragma unroll
        for (int d4 = lane; d4 < DRNN / 4; d4 += 32) {
            const float4 q = qr[d4];
            const float4 h = reinterpret_cast<const float4*>(ahs_s)[d4];
            acc += q.x * h.x + q.y * h.y + q.z * h.z + q.w * h.w;
        }
        #pragma unroll
        for (int off = 16; off; off >>= 1) acc += __shfl_xor_sync(0xffffffffu, acc, off);
        if (lane == 0) g_pq[b * DATT + a] = acc;
    }
}

// ---------------------------------------------------------------------------
// Kernel B (mega): conv + dense + tanh + value-dot + partial softmax
//                  + unnormalized context partial accumulation (fused)
// Block = 512 threads, 128 t's. grid (16, B). L2-prefetch of mem slice up top.
// ---------------------------------------------------------------------------
__global__ __launch_bounds__(512, 2) void align_kernel(
    const float* __restrict__ pm,      // [B,T,128]
    const float* __restrict__ mem,     // [B,T,512]
    const float* __restrict__ awc,     // [B,2,T]
    const float* __restrict__ convw,   // [32,2,31]
    const float* __restrict__ vw,      // [128]
    const unsigned char* __restrict__ mask,  // [B,T]
    float* __restrict__ wts_out)       // [B,T] exp-shifted (unnormalized)
{
    const int b = blockIdx.y;
    const int t0 = blockIdx.x * 128;
    const int tid = threadIdx.x;
    const int w = tid >> 5, lane = tid & 31;
    const int tq = w >> 2, aw = w & 3;
    const int tg = lane >> 2, ag = lane & 3;

    __shared__ __align__(16) float pq_s[DATT];
    __shared__ __align__(16) float val_s[DATT];
    __shared__ __align__(16) float dense_s[NFQ * DATT];   // [f][a]
    __shared__ float convw_s[NFQ * 2 * KW];
    __shared__ float awc_s[2][158];                       // 128 + 2*15
    __shared__ __align__(16) float loc_s[NFQ * 128];      // [f][tt]; reused as scratch
    __shared__ float part_s[4][4][32];                    // [tq][aw][tt]
    __shared__ float redm_s[4], reds_s[4];
    __shared__ float ew_s[128];

    const int abase = aw * 32 + ag * 8;
    const int tloc = tq * 32 + tg * 4;

    // ---- fire-and-forget L2 prefetch of this block's mem slice (256KB) ----
    {
        const float* mbase = mem + ((size_t)b * TT + t0) * DENC;
        #pragma unroll
        for (int i = 0; i < 4; i++)
            asm volatile("prefetch.global.L2 [%0];"
                         :: "l"(mbase + (size_t)(tid + i * 512) * 32));
    }

    // ---- stage shared (coalesced) ----
    if (tid < DATT) { pq_s[tid] = g_pq[b * DATT + tid]; val_s[tid] = vw[tid]; }
    #pragma unroll
    for (int i = tid; i < NFQ * DATT / 4; i += 512)
        reinterpret_cast<float4*>(dense_s)[i] = reinterpret_cast<const float4*>(g_dfa)[i];
    for (int i = tid; i < NFQ * 2 * KW; i += 512) convw_s[i] = convw[i];
    if (tid < 316) {
        int c = tid / 158, p = tid - c * 158;
        int pos = t0 - PADW + p;
        awc_s[c][p] = (pos >= 0 && pos < TT) ? awc[((size_t)b * 2 + c) * TT + pos] : 0.f;
    }
    __syncthreads();

    // ---- conv: thread computes f = tid>>4, tt range [(tid&15)*8, +8) ----
    {
        const int f = tid >> 4;
        const int ttb = (tid & 15) * 8;
        const float* cw = convw_s + f * 62;
        float acc[8], w0r[8], w1r[8];
        #pragma unroll
        for (int j = 0; j < 8; j++) {
            acc[j] = 0.f;
            w0r[j] = awc_s[0][ttb + j];
            w1r[j] = awc_s[1][ttb + j];
        }
        #pragma unroll
        for (int k = 0; k < KW; k++) {
            const float wk0 = cw[k], wk1 = cw[KW + k];
            #pragma unroll
            for (int j = 0; j < 8; j++) {
                const int r = (k + j) & 7;
                acc[j] += w0r[r] * wk0 + w1r[r] * wk1;
            }
            if (k < KW - 1) {
                w0r[k & 7] = awc_s[0][ttb + k + 8];
                w1r[k & 7] = awc_s[1][ttb + k + 8];
            }
        }
        #pragma unroll
        for (int j = 0; j < 8; j++) loc_s[f * 128 + ttb + j] = acc[j];
    }
    __syncthreads();

    // ---- dense (packed f32x2): lane tile = 4t x 8a ----
    ull acc2p[4][4];
    #pragma unroll
    for (int i = 0; i < 4; i++)
        #pragma unroll
        for (int jj = 0; jj < 4; jj++) acc2p[i][jj] = 0ull;

    #pragma unroll 4
    for (int f = 0; f < NFQ; f++) {
        const float4 lv = *reinterpret_cast<const float4*>(&loc_s[f * 128 + tloc]);
        const ulonglong2* dp =
            reinterpret_cast<const ulonglong2*>(&dense_s[f * DATT + abase]);
        const ulonglong2 q0 = dp[0], q1 = dp[1];
        const ull dvp[4] = {q0.x, q0.y, q1.x, q1.y};
        ull lvp[4];
        lvp[0] = pack2(lv.x, lv.x);
        lvp[1] = pack2(lv.y, lv.y);
        lvp[2] = pack2(lv.z, lv.z);
        lvp[3] = pack2(lv.w, lv.w);
        #pragma unroll
        for (int i = 0; i < 4; i++)
            #pragma unroll
            for (int jj = 0; jj < 4; jj++)
                acc2p[i][jj] = fma2(lvp[i], dvp[jj], acc2p[i][jj]);
    }

    const ulonglong2* pqp = reinterpret_cast<const ulonglong2*>(&pq_s[abase]);
    const ulonglong2 pqa = pqp[0], pqb = pqp[1];
    const ull pq2[4] = {pqa.x, pqa.y, pqb.x, pqb.y};
    float vr[8];
    #pragma unroll
    for (int j = 0; j < 8; j++) vr[j] = val_s[abase + j];

    // ---- energies + partial value-dot ----
    #pragma unroll
    for (int i = 0; i < 4; i++) {
        const int t = t0 + tloc + i;
        const ulonglong2* pmp = reinterpret_cast<const ulonglong2*>(
            pm + ((size_t)b * TT + t) * DATT + abase);
        const ulonglong2 m0 = pmp[0], m1 = pmp[1];
        const ull pv[4] = {m0.x, m0.y, m1.x, m1.y};
        float s = 0.f;
        #pragma unroll
        for (int jj = 0; jj < 4; jj++) {
            const ull e2 = add2(add2(pq2[jj], pv[jj]), acc2p[i][jj]);
            float elo, ehi;
            unpack2(e2, elo, ehi);
            s += tanh_fast(elo) * vr[2 * jj] + tanh_fast(ehi) * vr[2 * jj + 1];
        }
        s += __shfl_xor_sync(0xffffffffu, s, 1);
        s += __shfl_xor_sync(0xffffffffu, s, 2);
        if (ag == 0) part_s[tq][aw][tg * 4 + i] = s;
    }
    __syncthreads();

    // ---- partial softmax over this block's 128 t's ----
    const bool active = tid < 128;
    float sval = -INFINITY;
    if (active) {
        const int th = tid >> 5, tt = tid & 31;
        sval = part_s[th][0][tt] + part_s[th][1][tt] +
               part_s[th][2][tt] + part_s[th][3][tt];
        if (mask[(size_t)b * TT + t0 + tid]) sval = -INFINITY;
    }
    float m = sval;
    #pragma unroll
    for (int o = 16; o; o >>= 1) m = fmaxf(m, __shfl_xor_sync(0xffffffffu, m, o));
    if (active && lane == 0) redm_s[tid >> 5] = m;
    __syncthreads();
    const float Mb = fmaxf(fmaxf(redm_s[0], redm_s[1]), fmaxf(redm_s[2], redm_s[3]));
    float e = 0.f;
    if (active) {
        e = (sval == -INFINITY) ? 0.f : __expf(sval - Mb);
        ew_s[tid] = e;
        wts_out[(size_t)b * TT + t0 + tid] = e;   // unnormalized; fixed in reduce
    }
    float es = e;
    #pragma unroll
    for (int o = 16; o; o >>= 1) es += __shfl_xor_sync(0xffffffffu, es, o);
    if (active && lane == 0) reds_s[tid >> 5] = es;
    __syncthreads();
    if (tid == 0) {
        g_smax[b * SMX + blockIdx.x] = Mb;
        g_ssum[b * SMX + blockIdx.x] = reds_s[0] + reds_s[1] + reds_s[2] + reds_s[3];
    }

    // ---- fused context accumulation (unnormalized): stream mem slice ----
    // thread: d4 = tid & 127 (owns 4 d's), trow = tid >> 7 (0..3)
    const int d4 = tid & 127;
    const int trow = tid >> 7;
    const float4* mrow = reinterpret_cast<const float4*>(
        mem + ((size_t)b * TT + t0) * DENC) + d4;
    float4 cacc = make_float4(0.f, 0.f, 0.f, 0.f);
    #pragma unroll 8
    for (int i = trow; i < 128; i += 4) {
        const float ev = ew_s[i];
        const float4 mv = mrow[(size_t)i * (DENC / 4)];
        cacc.x += ev * mv.x;
        cacc.y += ev * mv.y;
        cacc.z += ev * mv.z;
        cacc.w += ev * mv.w;
    }
    // reduce across trow groups (reuse loc_s as scratch)
    float4* sc = reinterpret_cast<float4*>(loc_s);
    if (trow > 0) sc[(trow - 1) * 128 + d4] = cacc;
    __syncthreads();
    if (trow == 0) {
        #pragma unroll
        for (int r = 0; r < 3; r++) {
            const float4 p = sc[r * 128 + d4];
            cacc.x += p.x; cacc.y += p.y; cacc.z += p.z; cacc.w += p.w;
        }
        reinterpret_cast<float4*>(
            g_part + ((size_t)b * SMX + blockIdx.x) * DENC)[d4] = cacc;
    }
}

// ---------------------------------------------------------------------------
// Kernel E: stats combine + scaled reduce -> context; normalize weights
// 512 threads: s-loop split 4 ways (tid>>7), partials via smem.
// ---------------------------------------------------------------------------
__global__ __launch_bounds__(512) void ctx_reduce(float* __restrict__ ctx,
                                                  float* __restrict__ wts) {
    const int b = blockIdx.x;
    const int tid = threadIdx.x;
    const int lane = tid & 31;
    const int d4 = tid & 127;
    const int sgrp = tid >> 7;   // 0..3, each handles 4 s's
    __shared__ float scale_s[SMX];
    __shared__ __align__(16) float4 sc_s[3 * 128];

    if (tid < 32) {
        const float mi = (lane < SMX) ? g_smax[b * SMX + lane] : -INFINITY;
        const float si = (lane < SMX) ? g_ssum[b * SMX + lane] : 0.f;
        float M = mi;
        #pragma unroll
        for (int o = 16; o; o >>= 1) M = fmaxf(M, __shfl_xor_sync(0xffffffffu, M, o));
        float p = (mi == -INFINITY) ? 0.f : si * __expf(mi - M);
        #pragma unroll
        for (int o = 16; o; o >>= 1) p += __shfl_xor_sync(0xffffffffu, p, o);
        if (lane < SMX)
            scale_s[lane] = (mi == -INFINITY) ? 0.f : __expf(mi - M) / p;
    }
    __syncthreads();

    float4 acc = make_float4(0.f, 0.f, 0.f, 0.f);
    #pragma unroll
    for (int j = 0; j < 4; j++) {
        const int s = sgrp * 4 + j;
        const float sc = scale_s[s];
        const float4 p = reinterpret_cast<const float4*>(
            g_part + ((size_t)b * SMX + s) * DENC)[d4];
        acc.x += sc * p.x; acc.y += sc * p.y; acc.z += sc * p.z; acc.w += sc * p.w;
    }
    if (sgrp > 0) sc_s[(sgrp - 1) * 128 + d4] = acc;
    __syncthreads();
    if (sgrp == 0) {
        #pragma unroll
        for (int r = 0; r < 3; r++) {
            const float4 p = sc_s[r * 128 + d4];
            acc.x += p.x; acc.y += p.y; acc.z += p.z; acc.w += p.w;
        }
        reinterpret_cast<float4*>(ctx + (size_t)b * DENC)[d4] = acc;
    }

    // normalize attention weights: wts[b, t] *= scale[t >> 7]
    #pragma unroll
    for (int i = 0; i < 4; i++) {
        const int t = i * 512 + tid;
        wts[(size_t)b * TT + t] *= scale_s[t >> 7];
    }
}

// ---------------------------------------------------------------------------
// Entry
// ---------------------------------------------------------------------------
extern "C" void kernel_launch(void* const* d_in, const int* in_sizes, int n_in,
                              void* d_out, int out_size) {
    const float* ahs    = (const float*)d_in[0];
    const float* mem    = (const float*)d_in[1];
    const float* pm     = (const float*)d_in[2];
    const float* awc    = (const float*)d_in[3];
    const unsigned char* mask = (const unsigned char*)d_in[4];
    const float* qw     = (const float*)d_in[5];
    const float* vw     = (const float*)d_in[6];
    const float* convw  = (const float*)d_in[7];
    const float* densew = (const float*)d_in[8];

    float* out = (float*)d_out;
    float* ctx = out;               // [B, D_ENC]
    float* wts = out + BB * DENC;   // [B, T]

    pq_kernel<<<dim3(BB, 8), 128>>>(ahs, qw, densew);
    align_kernel<<<dim3(SMX, BB), 512>>>(pm, mem, awc, convw, vw, mask, wts);
    ctx_reduce<<<BB, 512>>>(ctx, wts);
}

// round 13
// speedup vs baseline: 1.1213x; 1.1213x over previous
#include <cuda_runtime.h>
#include <math.h>
#include <stdint.h>

#define BB 64
#define TT 2048
#define DENC 512
#define DRNN 1024
#define DATT 128
#define NFQ 32
#define KW 31
#define PADW 15
#define SMX 16              // blocks per row (128 t's each == align tile)

typedef unsigned long long ull;

__device__ float g_pq[BB * DATT];
__device__ float g_part[BB * SMX * DENC];          // unnormalized ctx partials
__device__ __align__(16) float g_dfa[NFQ * DATT];  // densew transposed to [f][a]
__device__ float g_smax[BB * SMX];
__device__ float g_ssum[BB * SMX];

__device__ __forceinline__ float tanh_fast(float x) {
    float y;
    asm("tanh.approx.f32 %0, %1;" : "=f"(y) : "f"(x));
    return y;
}
__device__ __forceinline__ void unpack2(ull v, float& lo, float& hi) {
    asm("mov.b64 {%0, %1}, %2;" : "=f"(lo), "=f"(hi) : "l"(v));
}
__device__ __forceinline__ ull pack2(float lo, float hi) {
    ull r;
    asm("mov.b64 %0, {%1, %2};" : "=l"(r) : "f"(lo), "f"(hi));
    return r;
}
__device__ __forceinline__ ull fma2(ull a, ull b, ull c) {
    ull d;
    asm("fma.rn.f32x2 %0, %1, %2, %3;" : "=l"(d) : "l"(a), "l"(b), "l"(c));
    return d;
}
__device__ __forceinline__ ull add2(ull a, ull b) {
    ull d;
    asm("add.rn.f32x2 %0, %1, %2;" : "=l"(d) : "l"(a), "l"(b));
    return d;
}

// ---------------------------------------------------------------------------
// Prep: transpose densew [a][f] -> g_dfa [f][a]
// ---------------------------------------------------------------------------
__global__ __launch_bounds__(256) void prep_dense(const float* __restrict__ densew) {
    const int i = blockIdx.x * 256 + threadIdx.x;
    const int f = i >> 7, a = i & 127;
    g_dfa[i] = densew[a * NFQ + f];
}

// ---------------------------------------------------------------------------
// Kernel A: pq[b,a] = sum_d ahs[b,d] * qw[a,d]   grid (B, 8)
// ---------------------------------------------------------------------------
__global__ __launch_bounds__(128) void pq_kernel(const float* __restrict__ ahs,
                                                 const float* __restrict__ qw) {
    const int b = blockIdx.x;
    const int abase = blockIdx.y * 16;
    __shared__ __align__(16) float ahs_s[DRNN];
    for (int i = threadIdx.x; i < DRNN / 4; i += 128)
        reinterpret_cast<float4*>(ahs_s)[i] =
            reinterpret_cast<const float4*>(ahs + (size_t)b * DRNN)[i];
    __syncthreads();
    const int w = threadIdx.x >> 5, lane = threadIdx.x & 31;
    #pragma unroll
    for (int aa = 0; aa < 4; aa++) {
        const int a = abase + w * 4 + aa;
        const float4* qr = reinterpret_cast<const float4*>(qw + (size_t)a * DRNN);
        float acc = 0.f;
        #pragma unroll
        for (int d4 = lane; d4 < DRNN / 4; d4 += 32) {
            const float4 q = qr[d4];
            const float4 h = reinterpret_cast<const float4*>(ahs_s)[d4];
            acc += q.x * h.x + q.y * h.y + q.z * h.z + q.w * h.w;
        }
        #pragma unroll
        for (int off = 16; off; off >>= 1) acc += __shfl_xor_sync(0xffffffffu, acc, off);
        if (lane == 0) g_pq[b * DATT + a] = acc;
    }
}

// ---------------------------------------------------------------------------
// Kernel B (mega): conv + dense + tanh + value-dot + partial softmax
//                  + UNNORMALIZED context partial accumulation (fused)
// Block = 512 threads, 128 t's. grid (16, B).
// ---------------------------------------------------------------------------
__global__ __launch_bounds__(512, 2) void align_kernel(
    const float* __restrict__ pm,      // [B,T,128]
    const float* __restrict__ mem,     // [B,T,512]
    const float* __restrict__ awc,     // [B,2,T]
    const float* __restrict__ convw,   // [32,2,31]
    const float* __restrict__ vw,      // [128]
    const unsigned char* __restrict__ mask,  // [B,T]
    float* __restrict__ wts_out)       // [B,T] exp-shifted (unnormalized)
{
    const int b = blockIdx.y;
    const int t0 = blockIdx.x * 128;
    const int tid = threadIdx.x;
    const int w = tid >> 5, lane = tid & 31;
    const int tq = w >> 2, aw = w & 3;
    const int tg = lane >> 2, ag = lane & 3;

    __shared__ __align__(16) float pq_s[DATT];
    __shared__ __align__(16) float val_s[DATT];
    __shared__ __align__(16) float dense_s[NFQ * DATT];   // [f][a]
    __shared__ float convw_s[NFQ * 2 * KW];
    __shared__ float awc_s[2][158];                       // 128 + 2*15
    __shared__ __align__(16) float loc_s[NFQ * 128];      // [f][tt]; reused as ctx scratch
    __shared__ float part_s[4][4][32];                    // [tq][aw][tt]
    __shared__ float redm_s[4], reds_s[4];
    __shared__ float ew_s[128];

    const int abase = aw * 32 + ag * 8;
    const int tloc = tq * 32 + tg * 4;

    // ---- stage shared (coalesced) ----
    if (tid < DATT) { pq_s[tid] = g_pq[b * DATT + tid]; val_s[tid] = vw[tid]; }
    #pragma unroll
    for (int i = tid; i < NFQ * DATT / 4; i += 512)
        reinterpret_cast<float4*>(dense_s)[i] = reinterpret_cast<const float4*>(g_dfa)[i];
    for (int i = tid; i < NFQ * 2 * KW; i += 512) convw_s[i] = convw[i];
    if (tid < 316) {
        int c = tid / 158, p = tid - c * 158;
        int pos = t0 - PADW + p;
        awc_s[c][p] = (pos >= 0 && pos < TT) ? awc[((size_t)b * 2 + c) * TT + pos] : 0.f;
    }
    __syncthreads();

    // ---- conv: thread computes f = tid>>4, tt range [(tid&15)*8, +8) ----
    {
        const int f = tid >> 4;
        const int ttb = (tid & 15) * 8;
        const float* cw = convw_s + f * 62;
        float acc[8], w0r[8], w1r[8];
        #pragma unroll
        for (int j = 0; j < 8; j++) {
            acc[j] = 0.f;
            w0r[j] = awc_s[0][ttb + j];
            w1r[j] = awc_s[1][ttb + j];
        }
        #pragma unroll
        for (int k = 0; k < KW; k++) {
            const float wk0 = cw[k], wk1 = cw[KW + k];
            #pragma unroll
            for (int j = 0; j < 8; j++) {
                const int r = (k + j) & 7;
                acc[j] += w0r[r] * wk0 + w1r[r] * wk1;
            }
            if (k < KW - 1) {
                w0r[k & 7] = awc_s[0][ttb + k + 8];
                w1r[k & 7] = awc_s[1][ttb + k + 8];
            }
        }
        #pragma unroll
        for (int j = 0; j < 8; j++) loc_s[f * 128 + ttb + j] = acc[j];
    }
    __syncthreads();

    // ---- dense (packed f32x2): lane tile = 4t x 8a ----
    ull acc2p[4][4];
    #pragma unroll
    for (int i = 0; i < 4; i++)
        #pragma unroll
        for (int jj = 0; jj < 4; jj++) acc2p[i][jj] = 0ull;

    #pragma unroll 4
    for (int f = 0; f < NFQ; f++) {
        const float4 lv = *reinterpret_cast<const float4*>(&loc_s[f * 128 + tloc]);
        const ulonglong2* dp =
            reinterpret_cast<const ulonglong2*>(&dense_s[f * DATT + abase]);
        const ulonglong2 q0 = dp[0], q1 = dp[1];
        const ull dvp[4] = {q0.x, q0.y, q1.x, q1.y};
        ull lvp[4];
        lvp[0] = pack2(lv.x, lv.x);
        lvp[1] = pack2(lv.y, lv.y);
        lvp[2] = pack2(lv.z, lv.z);
        lvp[3] = pack2(lv.w, lv.w);
        #pragma unroll
        for (int i = 0; i < 4; i++)
            #pragma unroll
            for (int jj = 0; jj < 4; jj++)
                acc2p[i][jj] = fma2(lvp[i], dvp[jj], acc2p[i][jj]);
    }

    const ulonglong2* pqp = reinterpret_cast<const ulonglong2*>(&pq_s[abase]);
    const ulonglong2 pqa = pqp[0], pqb = pqp[1];
    const ull pq2[4] = {pqa.x, pqa.y, pqb.x, pqb.y};
    float vr[8];
    #pragma unroll
    for (int j = 0; j < 8; j++) vr[j] = val_s[abase + j];

    // ---- energies + partial value-dot ----
    #pragma unroll
    for (int i = 0; i < 4; i++) {
        const int t = t0 + tloc + i;
        const ulonglong2* pmp = reinterpret_cast<const ulonglong2*>(
            pm + ((size_t)b * TT + t) * DATT + abase);
        const ulonglong2 m0 = pmp[0], m1 = pmp[1];
        const ull pv[4] = {m0.x, m0.y, m1.x, m1.y};
        float s = 0.f;
        #pragma unroll
        for (int jj = 0; jj < 4; jj++) {
            const ull e2 = add2(add2(pq2[jj], pv[jj]), acc2p[i][jj]);
            float elo, ehi;
            unpack2(e2, elo, ehi);
            s += tanh_fast(elo) * vr[2 * jj] + tanh_fast(ehi) * vr[2 * jj + 1];
        }
        s += __shfl_xor_sync(0xffffffffu, s, 1);
        s += __shfl_xor_sync(0xffffffffu, s, 2);
        if (ag == 0) part_s[tq][aw][tg * 4 + i] = s;
    }
    __syncthreads();

    // ---- partial softmax over this block's 128 t's ----
    const bool active = tid < 128;
    float sval = -INFINITY;
    if (active) {
        const int th = tid >> 5, tt = tid & 31;
        sval = part_s[th][0][tt] + part_s[th][1][tt] +
               part_s[th][2][tt] + part_s[th][3][tt];
        if (mask[(size_t)b * TT + t0 + tid]) sval = -INFINITY;
    }
    float m = sval;
    #pragma unroll
    for (int o = 16; o; o >>= 1) m = fmaxf(m, __shfl_xor_sync(0xffffffffu, m, o));
    if (active && lane == 0) redm_s[tid >> 5] = m;
    __syncthreads();
    const float Mb = fmaxf(fmaxf(redm_s[0], redm_s[1]), fmaxf(redm_s[2], redm_s[3]));
    float e = 0.f;
    if (active) {
        e = (sval == -INFINITY) ? 0.f : __expf(sval - Mb);
        ew_s[tid] = e;
        wts_out[(size_t)b * TT + t0 + tid] = e;   // unnormalized; fixed in reduce
    }
    float es = e;
    #pragma unroll
    for (int o = 16; o; o >>= 1) es += __shfl_xor_sync(0xffffffffu, es, o);
    if (active && lane == 0) reds_s[tid >> 5] = es;
    __syncthreads();
    if (tid == 0) {
        g_smax[b * SMX + blockIdx.x] = Mb;
        g_ssum[b * SMX + blockIdx.x] = reds_s[0] + reds_s[1] + reds_s[2] + reds_s[3];
    }

    // ---- fused context accumulation (unnormalized): stream mem slice ----
    // thread: d4 = tid & 127 (owns 4 d's), trow = tid >> 7 (0..3)
    const int d4 = tid & 127;
    const int trow = tid >> 7;
    const float4* mrow = reinterpret_cast<const float4*>(
        mem + ((size_t)b * TT + t0) * DENC) + d4;
    float4 cacc = make_float4(0.f, 0.f, 0.f, 0.f);
    #pragma unroll 8
    for (int i = trow; i < 128; i += 4) {
        const float ev = ew_s[i];
        const float4 mv = mrow[(size_t)i * (DENC / 4)];
        cacc.x += ev * mv.x;
        cacc.y += ev * mv.y;
        cacc.z += ev * mv.z;
        cacc.w += ev * mv.w;
    }
    // reduce across trow groups (reuse loc_s as scratch)
    float4* sc = reinterpret_cast<float4*>(loc_s);
    if (trow > 0) sc[(trow - 1) * 128 + d4] = cacc;
    __syncthreads();
    if (trow == 0) {
        #pragma unroll
        for (int r = 0; r < 3; r++) {
            const float4 p = sc[r * 128 + d4];
            cacc.x += p.x; cacc.y += p.y; cacc.z += p.z; cacc.w += p.w;
        }
        reinterpret_cast<float4*>(
            g_part + ((size_t)b * SMX + blockIdx.x) * DENC)[d4] = cacc;
    }
}

// ---------------------------------------------------------------------------
// Kernel E: stats combine + scaled reduce -> context; normalize weights
// 512 threads: warp 0 stats; s-loop split 4 ways (tid>>7) with smem combine.
// ---------------------------------------------------------------------------
__global__ __launch_bounds__(512) void ctx_reduce(float* __restrict__ ctx,
                                                  float* __restrict__ wts) {
    const int b = blockIdx.x;
    const int tid = threadIdx.x;
    const int lane = tid & 31;
    const int d4 = tid & 127;
    const int sgrp = tid >> 7;   // 0..3, each handles 4 s's
    __shared__ float scale_s[SMX];
    __shared__ __align__(16) float4 sc_s[3 * 128];

    if (tid < 32) {
        const float mi = (lane < SMX) ? g_smax[b * SMX + lane] : -INFINITY;
        const float si = (lane < SMX) ? g_ssum[b * SMX + lane] : 0.f;
        float M = mi;
        #pragma unroll
        for (int o = 16; o; o >>= 1) M = fmaxf(M, __shfl_xor_sync(0xffffffffu, M, o));
        float p = (mi == -INFINITY) ? 0.f : si * __expf(mi - M);
        #pragma unroll
        for (int o = 16; o; o >>= 1) p += __shfl_xor_sync(0xffffffffu, p, o);
        if (lane < SMX)
            scale_s[lane] = (mi == -INFINITY) ? 0.f : __expf(mi - M) / p;
    }
    __syncthreads();

    float4 acc = make_float4(0.f, 0.f, 0.f, 0.f);
    #pragma unroll
    for (int j = 0; j < 4; j++) {
        const int s = sgrp * 4 + j;
        const float sc = scale_s[s];
        const float4 p = reinterpret_cast<const float4*>(
            g_part + ((size_t)b * SMX + s) * DENC)[d4];
        acc.x += sc * p.x; acc.y += sc * p.y; acc.z += sc * p.z; acc.w += sc * p.w;
    }
    if (sgrp > 0) sc_s[(sgrp - 1) * 128 + d4] = acc;
    __syncthreads();
    if (sgrp == 0) {
        #pragma unroll
        for (int r = 0; r < 3; r++) {
            const float4 p = sc_s[r * 128 + d4];
            acc.x += p.x; acc.y += p.y; acc.z += p.z; acc.w += p.w;
        }
        reinterpret_cast<float4*>(ctx + (size_t)b * DENC)[d4] = acc;
    }

    // normalize attention weights: wts[b, t] *= scale[t >> 7]
    #pragma unroll
    for (int i = 0; i < 4; i++) {
        const int t = i * 512 + tid;
        wts[(size_t)b * TT + t] *= scale_s[t >> 7];
    }
}

// ---------------------------------------------------------------------------
// Entry
// ---------------------------------------------------------------------------
extern "C" void kernel_launch(void* const* d_in, const int* in_sizes, int n_in,
                              void* d_out, int out_size) {
    const float* ahs    = (const float*)d_in[0];
    const float* mem    = (const float*)d_in[1];
    const float* pm     = (const float*)d_in[2];
    const float* awc    = (const float*)d_in[3];
    const unsigned char* mask = (const unsigned char*)d_in[4];
    const float* qw     = (const float*)d_in[5];
    const float* vw     = (const float*)d_in[6];
    const float* convw  = (const float*)d_in[7];
    const float* densew = (const float*)d_in[8];

    float* out = (float*)d_out;
    float* ctx = out;               // [B, D_ENC]
    float* wts = out + BB * DENC;   // [B, T]

    prep_dense<<<NFQ * DATT / 256, 256>>>(densew);
    pq_kernel<<<dim3(BB, 8), 128>>>(ahs, qw);
    align_kernel<<<dim3(SMX, BB), 512>>>(pm, mem, awc, convw, vw, mask, wts);
    ctx_reduce<<<BB, 512>>>(ctx, wts);
}

// round 14
// speedup vs baseline: 1.1250x; 1.0034x over previous
#include <cuda_runtime.h>
#include <math.h>
#include <stdint.h>

#define BB 64
#define TT 2048
#define DENC 512
#define DRNN 1024
#define DATT 128
#define NFQ 32
#define KW 31
#define PADW 15
#define SMX 16              // blocks per row (128 t's each == align tile)

typedef unsigned long long ull;

__device__ float g_pq[BB * DATT];
__device__ float g_part[BB * SMX * DENC];          // unnormalized ctx partials
__device__ __align__(16) float g_dfa[NFQ * DATT];  // densew transposed to [f][a]
__device__ float g_smax[BB * SMX];
__device__ float g_ssum[BB * SMX];

__device__ __forceinline__ float tanh_fast(float x) {
    float y;
    asm("tanh.approx.f32 %0, %1;" : "=f"(y) : "f"(x));
    return y;
}
__device__ __forceinline__ void unpack2(ull v, float& lo, float& hi) {
    asm("mov.b64 {%0, %1}, %2;" : "=f"(lo), "=f"(hi) : "l"(v));
}
__device__ __forceinline__ ull pack2(float lo, float hi) {
    ull r;
    asm("mov.b64 %0, {%1, %2};" : "=l"(r) : "f"(lo), "f"(hi));
    return r;
}
__device__ __forceinline__ ull fma2(ull a, ull b, ull c) {
    ull d;
    asm("fma.rn.f32x2 %0, %1, %2, %3;" : "=l"(d) : "l"(a), "l"(b), "l"(c));
    return d;
}
__device__ __forceinline__ ull add2(ull a, ull b) {
    ull d;
    asm("add.rn.f32x2 %0, %1, %2;" : "=l"(d) : "l"(a), "l"(b));
    return d;
}

// ---------------------------------------------------------------------------
// Prep: transpose densew [a][f] -> g_dfa [f][a]
// ---------------------------------------------------------------------------
__global__ __launch_bounds__(256) void prep_dense(const float* __restrict__ densew) {
    const int i = blockIdx.x * 256 + threadIdx.x;
    const int f = i >> 7, a = i & 127;
    g_dfa[i] = densew[a * NFQ + f];
}

// ---------------------------------------------------------------------------
// Kernel A: pq[b,a] = sum_d ahs[b,d] * qw[a,d]   grid (B, 16), 8 a's per block
// ---------------------------------------------------------------------------
__global__ __launch_bounds__(128) void pq_kernel(const float* __restrict__ ahs,
                                                 const float* __restrict__ qw) {
    const int b = blockIdx.x;
    const int abase = blockIdx.y * 8;
    __shared__ __align__(16) float ahs_s[DRNN];
    for (int i = threadIdx.x; i < DRNN / 4; i += 128)
        reinterpret_cast<float4*>(ahs_s)[i] =
            reinterpret_cast<const float4*>(ahs + (size_t)b * DRNN)[i];
    __syncthreads();
    const int w = threadIdx.x >> 5, lane = threadIdx.x & 31;
    #pragma unroll
    for (int aa = 0; aa < 2; aa++) {
        const int a = abase + w * 2 + aa;
        const float4* qr = reinterpret_cast<const float4*>(qw + (size_t)a * DRNN);
        float acc = 0.f;
        #pragma unroll
        for (int d4 = lane; d4 < DRNN / 4; d4 += 32) {
            const float4 q = qr[d4];
            const float4 h = reinterpret_cast<const float4*>(ahs_s)[d4];
            acc += q.x * h.x + q.y * h.y + q.z * h.z + q.w * h.w;
        }
        #pragma unroll
        for (int off = 16; off; off >>= 1) acc += __shfl_xor_sync(0xffffffffu, acc, off);
        if (lane == 0) g_pq[b * DATT + a] = acc;
    }
}

// ---------------------------------------------------------------------------
// Kernel B (mega): conv + dense + tanh + value-dot + partial softmax
//                  + UNNORMALIZED context partial accumulation (fused)
// Block = 512 threads, 128 t's. grid (16, B).
// ---------------------------------------------------------------------------
__global__ __launch_bounds__(512, 2) void align_kernel(
    const float* __restrict__ pm,      // [B,T,128]
    const float* __restrict__ mem,     // [B,T,512]
    const float* __restrict__ awc,     // [B,2,T]
    const float* __restrict__ convw,   // [32,2,31]
    const float* __restrict__ vw,      // [128]
    const unsigned char* __restrict__ mask,  // [B,T]
    float* __restrict__ wts_out)       // [B,T] exp-shifted (unnormalized)
{
    const int b = blockIdx.y;
    const int t0 = blockIdx.x * 128;
    const int tid = threadIdx.x;
    const int w = tid >> 5, lane = tid & 31;
    const int tq = w >> 2, aw = w & 3;
    const int tg = lane >> 2, ag = lane & 3;

    __shared__ __align__(16) float pq_s[DATT];
    __shared__ __align__(16) float val_s[DATT];
    __shared__ __align__(16) float dense_s[NFQ * DATT];   // [f][a]
    __shared__ float convw_s[NFQ * 2 * KW];
    __shared__ float awc_s[2][158];                       // 128 + 2*15
    __shared__ __align__(16) float loc_s[NFQ * 128];      // [f][tt]; reused as ctx scratch
    __shared__ float part_s[4][4][32];                    // [tq][aw][tt]
    __shared__ float redm_s[4];
    __shared__ float ew_s[128];

    const int abase = aw * 32 + ag * 8;
    const int tloc = tq * 32 + tg * 4;

    // ---- stage shared (coalesced) ----
    if (tid < DATT) { pq_s[tid] = g_pq[b * DATT + tid]; val_s[tid] = vw[tid]; }
    #pragma unroll
    for (int i = tid; i < NFQ * DATT / 4; i += 512)
        reinterpret_cast<float4*>(dense_s)[i] = reinterpret_cast<const float4*>(g_dfa)[i];
    for (int i = tid; i < NFQ * 2 * KW; i += 512) convw_s[i] = convw[i];
    if (tid < 316) {
        int c = tid / 158, p = tid - c * 158;
        int pos = t0 - PADW + p;
        awc_s[c][p] = (pos >= 0 && pos < TT) ? awc[((size_t)b * 2 + c) * TT + pos] : 0.f;
    }
    __syncthreads();

    // ---- conv: thread computes f = tid>>4, tt range [(tid&15)*8, +8) ----
    {
        const int f = tid >> 4;
        const int ttb = (tid & 15) * 8;
        const float* cw = convw_s + f * 62;
        float acc[8], w0r[8], w1r[8];
        #pragma unroll
        for (int j = 0; j < 8; j++) {
            acc[j] = 0.f;
            w0r[j] = awc_s[0][ttb + j];
            w1r[j] = awc_s[1][ttb + j];
        }
        #pragma unroll
        for (int k = 0; k < KW; k++) {
            const float wk0 = cw[k], wk1 = cw[KW + k];
            #pragma unroll
            for (int j = 0; j < 8; j++) {
                const int r = (k + j) & 7;
                acc[j] += w0r[r] * wk0 + w1r[r] * wk1;
            }
            if (k < KW - 1) {
                w0r[k & 7] = awc_s[0][ttb + k + 8];
                w1r[k & 7] = awc_s[1][ttb + k + 8];
            }
        }
        #pragma unroll
        for (int j = 0; j < 8; j++) loc_s[f * 128 + ttb + j] = acc[j];
    }
    __syncthreads();

    // ---- dense (packed f32x2): lane tile = 4t x 8a ----
    ull acc2p[4][4];
    #pragma unroll
    for (int i = 0; i < 4; i++)
        #pragma unroll
        for (int jj = 0; jj < 4; jj++) acc2p[i][jj] = 0ull;

    #pragma unroll 4
    for (int f = 0; f < NFQ; f++) {
        const float4 lv = *reinterpret_cast<const float4*>(&loc_s[f * 128 + tloc]);
        const ulonglong2* dp =
            reinterpret_cast<const ulonglong2*>(&dense_s[f * DATT + abase]);
        const ulonglong2 q0 = dp[0], q1 = dp[1];
        const ull dvp[4] = {q0.x, q0.y, q1.x, q1.y};
        ull lvp[4];
        lvp[0] = pack2(lv.x, lv.x);
        lvp[1] = pack2(lv.y, lv.y);
        lvp[2] = pack2(lv.z, lv.z);
        lvp[3] = pack2(lv.w, lv.w);
        #pragma unroll
        for (int i = 0; i < 4; i++)
            #pragma unroll
            for (int jj = 0; jj < 4; jj++)
                acc2p[i][jj] = fma2(lvp[i], dvp[jj], acc2p[i][jj]);
    }

    const ulonglong2* pqp = reinterpret_cast<const ulonglong2*>(&pq_s[abase]);
    const ulonglong2 pqa = pqp[0], pqb = pqp[1];
    const ull pq2[4] = {pqa.x, pqa.y, pqb.x, pqb.y};
    float vr[8];
    #pragma unroll
    for (int j = 0; j < 8; j++) vr[j] = val_s[abase + j];

    // ---- energies + partial value-dot ----
    #pragma unroll
    for (int i = 0; i < 4; i++) {
        const int t = t0 + tloc + i;
        const ulonglong2* pmp = reinterpret_cast<const ulonglong2*>(
            pm + ((size_t)b * TT + t) * DATT + abase);
        const ulonglong2 m0 = pmp[0], m1 = pmp[1];
        const ull pv[4] = {m0.x, m0.y, m1.x, m1.y};
        float s = 0.f;
        #pragma unroll
        for (int jj = 0; jj < 4; jj++) {
            const ull e2 = add2(add2(pq2[jj], pv[jj]), acc2p[i][jj]);
            float elo, ehi;
            unpack2(e2, elo, ehi);
            s += tanh_fast(elo) * vr[2 * jj] + tanh_fast(ehi) * vr[2 * jj + 1];
        }
        s += __shfl_xor_sync(0xffffffffu, s, 1);
        s += __shfl_xor_sync(0xffffffffu, s, 2);
        if (ag == 0) part_s[tq][aw][tg * 4 + i] = s;
    }
    __syncthreads();

    // ---- partial softmax over this block's 128 t's (minimal barriers) ----
    const bool active = tid < 128;
    float sval = -INFINITY;
    if (active) {
        const int th = tid >> 5, tt = tid & 31;
        sval = part_s[th][0][tt] + part_s[th][1][tt] +
               part_s[th][2][tt] + part_s[th][3][tt];
        if (mask[(size_t)b * TT + t0 + tid]) sval = -INFINITY;
    }
    float m = sval;
    #pragma unroll
    for (int o = 16; o; o >>= 1) m = fmaxf(m, __shfl_xor_sync(0xffffffffu, m, o));
    if (active && lane == 0) redm_s[tid >> 5] = m;
    __syncthreads();
    const float Mb = fmaxf(fmaxf(redm_s[0], redm_s[1]), fmaxf(redm_s[2], redm_s[3]));
    if (active) {
        const float e = (sval == -INFINITY) ? 0.f : __expf(sval - Mb);
        ew_s[tid] = e;
        wts_out[(size_t)b * TT + t0 + tid] = e;   // unnormalized; fixed in reduce
    }
    __syncthreads();   // publishes ew_s for BOTH stats (warp 0) and streaming (all)

    // warp 0 derives the block e-sum from ew_s — other 15 warps stream immediately
    if (tid < 32) {
        float es = ew_s[tid] + ew_s[tid + 32] + ew_s[tid + 64] + ew_s[tid + 96];
        #pragma unroll
        for (int o = 16; o; o >>= 1) es += __shfl_xor_sync(0xffffffffu, es, o);
        if (tid == 0) {
            g_smax[b * SMX + blockIdx.x] = Mb;
            g_ssum[b * SMX + blockIdx.x] = es;
        }
    }

    // ---- fused context accumulation (unnormalized): stream mem slice ----
    const int d4 = tid & 127;
    const int trow = tid >> 7;
    const float4* mrow = reinterpret_cast<const float4*>(
        mem + ((size_t)b * TT + t0) * DENC) + d4;
    float4 cacc = make_float4(0.f, 0.f, 0.f, 0.f);
    #pragma unroll 16
    for (int i = trow; i < 128; i += 4) {
        const float ev = ew_s[i];
        const float4 mv = mrow[(size_t)i * (DENC / 4)];
        cacc.x += ev * mv.x;
        cacc.y += ev * mv.y;
        cacc.z += ev * mv.z;
        cacc.w += ev * mv.w;
    }
    // reduce across trow groups (reuse loc_s as scratch)
    float4* sc = reinterpret_cast<float4*>(loc_s);
    if (trow > 0) sc[(trow - 1) * 128 + d4] = cacc;
    __syncthreads();
    if (trow == 0) {
        #pragma unroll
        for (int r = 0; r < 3; r++) {
            const float4 p = sc[r * 128 + d4];
            cacc.x += p.x; cacc.y += p.y; cacc.z += p.z; cacc.w += p.w;
        }
        reinterpret_cast<float4*>(
            g_part + ((size_t)b * SMX + blockIdx.x) * DENC)[d4] = cacc;
    }
}

// ---------------------------------------------------------------------------
// Kernel E: stats combine + scaled reduce -> context; normalize weights
// grid (4, B), 128 threads. Block q handles 32 float4 of d and 512 t's of wts.
// ---------------------------------------------------------------------------
__global__ __launch_bounds__(128) void ctx_reduce(float* __restrict__ ctx,
                                                  float* __restrict__ wts) {
    const int q = blockIdx.x, b = blockIdx.y;
    const int tid = threadIdx.x;
    const int lane = tid & 31, w = tid >> 5;
    __shared__ float scale_s[SMX];
    __shared__ __align__(16) float4 sc_s[3 * 32];

    if (tid < 32) {
        const float mi = (lane < SMX) ? g_smax[b * SMX + lane] : -INFINITY;
        const float si = (lane < SMX) ? g_ssum[b * SMX + lane] : 0.f;
        float M = mi;
        #pragma unroll
        for (int o = 16; o; o >>= 1) M = fmaxf(M, __shfl_xor_sync(0xffffffffu, M, o));
        float p = (mi == -INFINITY) ? 0.f : si * __expf(mi - M);
        #pragma unroll
        for (int o = 16; o; o >>= 1) p += __shfl_xor_sync(0xffffffffu, p, o);
        if (lane < SMX)
            scale_s[lane] = (mi == -INFINITY) ? 0.f : __expf(mi - M) / p;
    }
    __syncthreads();

    const int d4 = q * 32 + lane;
    float4 acc = make_float4(0.f, 0.f, 0.f, 0.f);
    #pragma unroll
    for (int j = 0; j < 4; j++) {
        const int s = w * 4 + j;
        const float sc = scale_s[s];
        const float4 p = reinterpret_cast<const float4*>(
            g_part + ((size_t)b * SMX + s) * DENC)[d4];
        acc.x += sc * p.x; acc.y += sc * p.y; acc.z += sc * p.z; acc.w += sc * p.w;
    }
    if (w > 0) sc_s[(w - 1) * 32 + lane] = acc;
    __syncthreads();
    if (w == 0) {
        #pragma unroll
        for (int r = 0; r < 3; r++) {
            const float4 p = sc_s[r * 32 + lane];
            acc.x += p.x; acc.y += p.y; acc.z += p.z; acc.w += p.w;
        }
        reinterpret_cast<float4*>(ctx + (size_t)b * DENC)[d4] = acc;
    }

    // normalize attention weights: block q covers t in [q*512, q*512+512)
    #pragma unroll
    for (int i = 0; i < 4; i++) {
        const int t = q * 512 + i * 128 + tid;
        wts[(size_t)b * TT + t] *= scale_s[t >> 7];
    }
}

// ---------------------------------------------------------------------------
// Entry
// ---------------------------------------------------------------------------
extern "C" void kernel_launch(void* const* d_in, const int* in_sizes, int n_in,
                              void* d_out, int out_size) {
    const float* ahs    = (const float*)d_in[0];
    const float* mem    = (const float*)d_in[1];
    const float* pm     = (const float*)d_in[2];
    const float* awc    = (const float*)d_in[3];
    const unsigned char* mask = (const unsigned char*)d_in[4];
    const float* qw     = (const float*)d_in[5];
    const float* vw     = (const float*)d_in[6];
    const float* convw  = (const float*)d_in[7];
    const float* densew = (const float*)d_in[8];

    float* out = (float*)d_out;
    float* ctx = out;               // [B, D_ENC]
    float* wts = out + BB * DENC;   // [B, T]

    prep_dense<<<NFQ * DATT / 256, 256>>>(densew);
    pq_kernel<<<dim3(BB, 16), 128>>>(ahs, qw);
    align_kernel<<<dim3(SMX, BB), 512>>>(pm, mem, awc, convw, vw, mask, wts);
    ctx_reduce<<<dim3(4, BB), 128>>>(ctx, wts);
}